// round 13
// baseline (speedup 1.0000x reference)
#include <cuda_runtime.h>
#include <cuda_fp16.h>
#include <cstdint>

// SigCubicalEcc round 13 = round 12 + tanh.approx.f16x2 (one MUFU op per
// 2 steps) + relu-form contribution (exact algebraic rewrite):
//   contrib = relu(mp0-m0) + relu(mp1-m1) - relu(sp0-s0) - relu(sp1-s1)
//   (lane 0: the sp0 relu term is dropped -- left-boundary cancellation).
// h = tanh(100*(t_j - x)); ECC_j = 0.5 * signed h-sum + 0.5. Padding h = -1.
// 256 thr, 8 warps x 8 rows, GROUPS=16 (2 steps packed in half2), 1 launch.

#define HH 64
#define WW 64
#define STEPS 32
#define GROUPS 16
#define SPG 2
#define THREADS 256
#define NWARP 8
#define ROWS_PER_WARP 8
#define NIMG 192

__device__ __forceinline__ uint32_t h2_as_u32(__half2 v) {
    return *reinterpret_cast<uint32_t*>(&v);
}
__device__ __forceinline__ __half2 u32_as_h2(uint32_t u) {
    return *reinterpret_cast<__half2*>(&u);
}
__device__ __forceinline__ __half2 tanh2_approx(__half2 v) {
    uint32_t r, u = h2_as_u32(v);
    asm("tanh.approx.f16x2 %0, %1;" : "=r"(r) : "r"(u));
    return u32_as_h2(r);
}

__global__ __launch_bounds__(THREADS, 8)
void sig_cubical_ecc_kernel(const float* __restrict__ x, float* __restrict__ out) {
    __shared__ float red[NWARP][SPG];

    const int img   = blockIdx.x >> 4;           // / GROUPS
    const int group = blockIdx.x & (GROUPS - 1);
    const int tid   = threadIdx.x;
    const int lane  = tid & 31;
    const int warp  = tid >> 5;

    const float HL = 100.0f;                     // LAM / 2

    const int j0 = group * SPG;
    const float A0 = HL * (0.02f + (float)(j0 + 0) * (0.26f / 31.0f));
    const float A1 = HL * (0.02f + (float)(j0 + 1) * (0.26f / 31.0f));

    const __half2 NEG1 = __floats2half2_rn(-1.0f, -1.0f);
    const __half2 ZERO = __floats2half2_rn(0.0f, 0.0f);

    const float* xi = x + (size_t)img * (HH * WW) + 2 * lane;
    const int r0 = warp * ROWS_PER_WARP;

    __half2 sp0 = NEG1, sp1 = NEG1, mp0 = NEG1, mp1 = NEG1;  // padding h = -1
    float accx = 0.0f, accy = 0.0f;

    // ---- halo row r0-1 (warp 0: row -1 is padding => keep NEG1 init) ----
    if (warp > 0) {
        float2 xv = *reinterpret_cast<const float2*>(xi + (r0 - 1) * WW);
        __half2 s0 = tanh2_approx(__floats2half2_rn(fmaf(xv.x, -HL, A0),
                                                    fmaf(xv.x, -HL, A1)));
        __half2 s1 = tanh2_approx(__floats2half2_rn(fmaf(xv.y, -HL, A0),
                                                    fmaf(xv.y, -HL, A1)));
        uint32_t snu = __shfl_down_sync(0xffffffffu, h2_as_u32(s0), 1);
        __half2 sn = (lane == 31) ? NEG1 : u32_as_h2(snu);
        sp0 = s0; sp1 = s1;
        mp0 = __hmax2(s0, s1);
        mp1 = __hmax2(s1, sn);
    }

    // ---- 8 data rows ----
#pragma unroll
    for (int i = 0; i < ROWS_PER_WARP; i++) {
        float2 xv = *reinterpret_cast<const float2*>(xi + (r0 + i) * WW);
        __half2 s0 = tanh2_approx(__floats2half2_rn(fmaf(xv.x, -HL, A0),
                                                    fmaf(xv.x, -HL, A1)));
        __half2 s1 = tanh2_approx(__floats2half2_rn(fmaf(xv.y, -HL, A0),
                                                    fmaf(xv.y, -HL, A1)));
        uint32_t snu = __shfl_down_sync(0xffffffffu, h2_as_u32(s0), 1);
        __half2 sn = (lane == 31) ? NEG1 : u32_as_h2(snu);

        __half2 m0 = __hmax2(s0, s1);
        __half2 m1 = __hmax2(s1, sn);

        __half2 ra = __hmax2(__hsub2(mp0, m0), ZERO);   // relu(mp0 - m0)
        __half2 rb = __hmax2(__hsub2(mp1, m1), ZERO);   // relu(mp1 - m1)
        __half2 rc = __hmax2(__hsub2(sp0, s0), ZERO);   // relu(sp0 - s0)
        rc = (lane == 0) ? ZERO : rc;                   // left-boundary cancel
        __half2 rd = __hmax2(__hsub2(sp1, s1), ZERO);   // relu(sp1 - s1)

        __half2 contrib = __hsub2(__hadd2(ra, rb), __hadd2(rc, rd));
        float2 cf = __half22float2(contrib);
        accx += cf.x;
        accy += cf.y;

        sp0 = s0; sp1 = s1; mp0 = m0; mp1 = m1;
    }

    // ---- bottom boundary (row below is padding) -- byte-identical to R12 ----
    if (warp == NWARP - 1) {
        __half2 ehsel = (lane == 0) ? ZERO : sp0;
        __half2 c = __hadd2(__hsub2(mp0, ehsel), __hsub2(mp1, sp1));
        float2 cf = __half22float2(c);
        accx += cf.x;
        accy += cf.y;
    }

    // ---- warp reduce, then block reduce in smem, single store ----
#pragma unroll
    for (int o = 16; o > 0; o >>= 1) {
        accx += __shfl_xor_sync(0xffffffffu, accx, o);
        accy += __shfl_xor_sync(0xffffffffu, accy, o);
    }
    if (lane == 0) { red[warp][0] = accx; red[warp][1] = accy; }
    __syncthreads();

    if (tid < SPG) {
        float s = 0.0f;
#pragma unroll
        for (int w = 0; w < NWARP; w++) s += red[w][tid];
        // ECC = 0.5 * signed h-sum + 0.5 (V - Eh - Ev + F counts = 1)
        out[img * STEPS + group * SPG + tid] = 0.5f * s + 0.5f;
    }
}

extern "C" void kernel_launch(void* const* d_in, const int* in_sizes, int n_in,
                              void* d_out, int out_size) {
    const float* x = (const float*)d_in[0];
    float* out = (float*)d_out;

    sig_cubical_ecc_kernel<<<NIMG * GROUPS, THREADS>>>(x, out);
}

// round 14
// speedup vs baseline: 1.0753x; 1.0753x over previous
#include <cuda_runtime.h>
#include <cuda_fp16.h>
#include <cstdint>

// SigCubicalEcc round 14 = round 12 (proven) + two verified op cuts:
//   (1) tanh.approx.f16x2 (2 MUFU ops/row instead of 4; same arg prep)
//   (2) half2 accumulation across the 8-row loop (1 HADD2/row instead of
//       CVT + 2 FADD), converted to f32 once per warp.
// Contribution formula is byte-identical to round 12.
//
// h = tanh(100*(t_j - x)) = 2*sigma - 1 (monotone => max-decomposition holds
// with padding h = -1):  ECC_j = 0.5 * [signed h-sum over cells] + 0.5.
// 256 thr, 8 warps x 8 rows, GROUPS=16 (2 steps packed in half2), 1 launch.

#define HH 64
#define WW 64
#define STEPS 32
#define GROUPS 16
#define SPG 2
#define THREADS 256
#define NWARP 8
#define ROWS_PER_WARP 8
#define NIMG 192

__device__ __forceinline__ uint32_t h2_as_u32(__half2 v) {
    return *reinterpret_cast<uint32_t*>(&v);
}
__device__ __forceinline__ __half2 u32_as_h2(uint32_t u) {
    return *reinterpret_cast<__half2*>(&u);
}
__device__ __forceinline__ __half2 tanh2_approx(__half2 v) {
    uint32_t r, u = h2_as_u32(v);
    asm("tanh.approx.f16x2 %0, %1;" : "=r"(r) : "r"(u));
    return u32_as_h2(r);
}

__global__ __launch_bounds__(THREADS, 8)
void sig_cubical_ecc_kernel(const float* __restrict__ x, float* __restrict__ out) {
    __shared__ float red[NWARP][SPG];

    const int img   = blockIdx.x >> 4;           // / GROUPS
    const int group = blockIdx.x & (GROUPS - 1);
    const int tid   = threadIdx.x;
    const int lane  = tid & 31;
    const int warp  = tid >> 5;

    const float HL = 100.0f;                     // LAM / 2

    const int j0 = group * SPG;
    const float A0 = HL * (0.02f + (float)(j0 + 0) * (0.26f / 31.0f));
    const float A1 = HL * (0.02f + (float)(j0 + 1) * (0.26f / 31.0f));

    const __half2 NEG1 = __floats2half2_rn(-1.0f, -1.0f);
    const __half2 ZERO = __floats2half2_rn(0.0f, 0.0f);

    const float* xi = x + (size_t)img * (HH * WW) + 2 * lane;
    const int r0 = warp * ROWS_PER_WARP;

    __half2 sp0 = NEG1, sp1 = NEG1, mp0 = NEG1, mp1 = NEG1;  // padding h = -1
    __half2 acc = ZERO;

    // ---- halo row r0-1 (warp 0: row -1 is padding => keep NEG1 init) ----
    if (warp > 0) {
        float2 xv = *reinterpret_cast<const float2*>(xi + (r0 - 1) * WW);
        __half2 s0 = tanh2_approx(__floats2half2_rn(fmaf(xv.x, -HL, A0),
                                                    fmaf(xv.x, -HL, A1)));
        __half2 s1 = tanh2_approx(__floats2half2_rn(fmaf(xv.y, -HL, A0),
                                                    fmaf(xv.y, -HL, A1)));
        uint32_t snu = __shfl_down_sync(0xffffffffu, h2_as_u32(s0), 1);
        __half2 sn = (lane == 31) ? NEG1 : u32_as_h2(snu);
        sp0 = s0; sp1 = s1;
        mp0 = __hmax2(s0, s1);
        mp1 = __hmax2(s1, sn);
    }

    // ---- 8 data rows ----
#pragma unroll
    for (int i = 0; i < ROWS_PER_WARP; i++) {
        float2 xv = *reinterpret_cast<const float2*>(xi + (r0 + i) * WW);
        __half2 s0 = tanh2_approx(__floats2half2_rn(fmaf(xv.x, -HL, A0),
                                                    fmaf(xv.x, -HL, A1)));
        __half2 s1 = tanh2_approx(__floats2half2_rn(fmaf(xv.y, -HL, A0),
                                                    fmaf(xv.y, -HL, A1)));
        uint32_t snu = __shfl_down_sync(0xffffffffu, h2_as_u32(s0), 1);
        __half2 sn = (lane == 31) ? NEG1 : u32_as_h2(snu);

        __half2 m0 = __hmax2(s0, s1);
        __half2 m1 = __hmax2(s1, sn);

        __half2 eh    = __hmax2(s0, sp0);
        __half2 ehsel = (lane == 0) ? s0 : eh;   // left-boundary cancellation
        __half2 contrib =
            __hadd2(__hsub2(__hmin2(s0, s1), m1),
            __hadd2(__hsub2(__hmax2(m0, mp0), ehsel),
                    __hsub2(__hmax2(m1, mp1), __hmax2(s1, sp1))));
        acc = __hadd2(acc, contrib);

        sp0 = s0; sp1 = s1; mp0 = m0; mp1 = m1;
    }

    // ---- bottom boundary (row below is padding) ----
    if (warp == NWARP - 1) {
        __half2 ehsel = (lane == 0) ? ZERO : sp0;
        acc = __hadd2(acc, __hadd2(__hsub2(mp0, ehsel), __hsub2(mp1, sp1)));
    }

    // ---- convert once, warp reduce in f32, block reduce, store ----
    float2 af = __half22float2(acc);
    float accx = af.x, accy = af.y;
#pragma unroll
    for (int o = 16; o > 0; o >>= 1) {
        accx += __shfl_xor_sync(0xffffffffu, accx, o);
        accy += __shfl_xor_sync(0xffffffffu, accy, o);
    }
    if (lane == 0) { red[warp][0] = accx; red[warp][1] = accy; }
    __syncthreads();

    if (tid < SPG) {
        float s = 0.0f;
#pragma unroll
        for (int w = 0; w < NWARP; w++) s += red[w][tid];
        // ECC = 0.5 * signed h-sum + 0.5 (V - Eh - Ev + F counts = 1)
        out[img * STEPS + group * SPG + tid] = 0.5f * s + 0.5f;
    }
}

extern "C" void kernel_launch(void* const* d_in, const int* in_sizes, int n_in,
                              void* d_out, int out_size) {
    const float* x = (const float*)d_in[0];
    float* out = (float*)d_out;

    sig_cubical_ecc_kernel<<<NIMG * GROUPS, THREADS>>>(x, out);
}

// round 15
// speedup vs baseline: 1.1572x; 1.0762x over previous
#include <cuda_runtime.h>
#include <cuda_fp16.h>
#include <cstdint>

// SigCubicalEcc round 15 = round 14 body with GROUPS=8: each block handles
// 4 steps as TWO independent half2 chains (ILP + amortized row overhead).
//
// h = tanh(100*(t_j - x)) = 2*sigma - 1 (monotone => max-decomposition holds
// with padding h = -1):  ECC_j = 0.5 * [signed h-sum over cells] + 0.5.
// tanh.approx.f16x2; half2 accumulation; f32 conversion once per warp.
// 256 thr, 8 warps x 8 rows, grid = 192 * 8 = 1536, single launch.

#define HH 64
#define WW 64
#define STEPS 32
#define GROUPS 8
#define SPG 4                   // 4 steps = 2 half2 chains
#define THREADS 256
#define NWARP 8
#define ROWS_PER_WARP 8
#define NIMG 192

__device__ __forceinline__ uint32_t h2_as_u32(__half2 v) {
    return *reinterpret_cast<uint32_t*>(&v);
}
__device__ __forceinline__ __half2 u32_as_h2(uint32_t u) {
    return *reinterpret_cast<__half2*>(&u);
}
__device__ __forceinline__ __half2 tanh2_approx(__half2 v) {
    uint32_t r, u = h2_as_u32(v);
    asm("tanh.approx.f16x2 %0, %1;" : "=r"(r) : "r"(u));
    return u32_as_h2(r);
}

struct Chain {
    __half2 sp0, sp1, mp0, mp1, acc;
};

__device__ __forceinline__ void halo_update(Chain& ch, __half2 s0, __half2 s1,
                                            __half2 sn) {
    ch.sp0 = s0; ch.sp1 = s1;
    ch.mp0 = __hmax2(s0, s1);
    ch.mp1 = __hmax2(s1, sn);
}

__device__ __forceinline__ void row_update(Chain& ch, __half2 s0, __half2 s1,
                                           __half2 sn, bool lane0) {
    __half2 m0 = __hmax2(s0, s1);
    __half2 m1 = __hmax2(s1, sn);
    __half2 eh    = __hmax2(s0, ch.sp0);
    __half2 ehsel = lane0 ? s0 : eh;             // left-boundary cancellation
    __half2 contrib =
        __hadd2(__hsub2(__hmin2(s0, s1), m1),
        __hadd2(__hsub2(__hmax2(m0, ch.mp0), ehsel),
                __hsub2(__hmax2(m1, ch.mp1), __hmax2(s1, ch.sp1))));
    ch.acc = __hadd2(ch.acc, contrib);
    ch.sp0 = s0; ch.sp1 = s1; ch.mp0 = m0; ch.mp1 = m1;
}

__global__ __launch_bounds__(THREADS, 6)
void sig_cubical_ecc_kernel(const float* __restrict__ x, float* __restrict__ out) {
    __shared__ float red[NWARP][SPG];

    const int img   = blockIdx.x >> 3;           // / GROUPS
    const int group = blockIdx.x & (GROUPS - 1);
    const int tid   = threadIdx.x;
    const int lane  = tid & 31;
    const int warp  = tid >> 5;
    const bool lane0 = (lane == 0);

    const float HL = 100.0f;                     // LAM / 2

    const int j0 = group * SPG;
    const float A0 = HL * (0.02f + (float)(j0 + 0) * (0.26f / 31.0f));
    const float A1 = HL * (0.02f + (float)(j0 + 1) * (0.26f / 31.0f));
    const float A2 = HL * (0.02f + (float)(j0 + 2) * (0.26f / 31.0f));
    const float A3 = HL * (0.02f + (float)(j0 + 3) * (0.26f / 31.0f));

    const __half2 NEG1 = __floats2half2_rn(-1.0f, -1.0f);
    const __half2 ZERO = __floats2half2_rn(0.0f, 0.0f);

    const float* xi = x + (size_t)img * (HH * WW) + 2 * lane;
    const int r0 = warp * ROWS_PER_WARP;

    Chain ca, cb;
    ca.sp0 = NEG1; ca.sp1 = NEG1; ca.mp0 = NEG1; ca.mp1 = NEG1; ca.acc = ZERO;
    cb.sp0 = NEG1; cb.sp1 = NEG1; cb.mp0 = NEG1; cb.mp1 = NEG1; cb.acc = ZERO;

    // ---- halo row r0-1 (warp 0: row -1 is padding => keep NEG1 init) ----
    if (warp > 0) {
        float2 xv = *reinterpret_cast<const float2*>(xi + (r0 - 1) * WW);
        __half2 sa0 = tanh2_approx(__floats2half2_rn(fmaf(xv.x, -HL, A0),
                                                     fmaf(xv.x, -HL, A1)));
        __half2 sa1 = tanh2_approx(__floats2half2_rn(fmaf(xv.y, -HL, A0),
                                                     fmaf(xv.y, -HL, A1)));
        __half2 sb0 = tanh2_approx(__floats2half2_rn(fmaf(xv.x, -HL, A2),
                                                     fmaf(xv.x, -HL, A3)));
        __half2 sb1 = tanh2_approx(__floats2half2_rn(fmaf(xv.y, -HL, A2),
                                                     fmaf(xv.y, -HL, A3)));
        uint32_t sna = __shfl_down_sync(0xffffffffu, h2_as_u32(sa0), 1);
        uint32_t snb = __shfl_down_sync(0xffffffffu, h2_as_u32(sb0), 1);
        halo_update(ca, sa0, sa1, (lane == 31) ? NEG1 : u32_as_h2(sna));
        halo_update(cb, sb0, sb1, (lane == 31) ? NEG1 : u32_as_h2(snb));
    }

    // ---- 8 data rows ----
#pragma unroll
    for (int i = 0; i < ROWS_PER_WARP; i++) {
        float2 xv = *reinterpret_cast<const float2*>(xi + (r0 + i) * WW);
        __half2 sa0 = tanh2_approx(__floats2half2_rn(fmaf(xv.x, -HL, A0),
                                                     fmaf(xv.x, -HL, A1)));
        __half2 sa1 = tanh2_approx(__floats2half2_rn(fmaf(xv.y, -HL, A0),
                                                     fmaf(xv.y, -HL, A1)));
        __half2 sb0 = tanh2_approx(__floats2half2_rn(fmaf(xv.x, -HL, A2),
                                                     fmaf(xv.x, -HL, A3)));
        __half2 sb1 = tanh2_approx(__floats2half2_rn(fmaf(xv.y, -HL, A2),
                                                     fmaf(xv.y, -HL, A3)));
        uint32_t sna = __shfl_down_sync(0xffffffffu, h2_as_u32(sa0), 1);
        uint32_t snb = __shfl_down_sync(0xffffffffu, h2_as_u32(sb0), 1);
        row_update(ca, sa0, sa1, (lane == 31) ? NEG1 : u32_as_h2(sna), lane0);
        row_update(cb, sb0, sb1, (lane == 31) ? NEG1 : u32_as_h2(snb), lane0);
    }

    // ---- bottom boundary (row below is padding) ----
    if (warp == NWARP - 1) {
        __half2 ehA = lane0 ? ZERO : ca.sp0;
        ca.acc = __hadd2(ca.acc, __hadd2(__hsub2(ca.mp0, ehA),
                                         __hsub2(ca.mp1, ca.sp1)));
        __half2 ehB = lane0 ? ZERO : cb.sp0;
        cb.acc = __hadd2(cb.acc, __hadd2(__hsub2(cb.mp0, ehB),
                                         __hsub2(cb.mp1, cb.sp1)));
    }

    // ---- convert once, warp reduce in f32, block reduce, store ----
    float2 fa = __half22float2(ca.acc);
    float2 fb = __half22float2(cb.acc);
    float a0 = fa.x, a1 = fa.y, a2 = fb.x, a3 = fb.y;
#pragma unroll
    for (int o = 16; o > 0; o >>= 1) {
        a0 += __shfl_xor_sync(0xffffffffu, a0, o);
        a1 += __shfl_xor_sync(0xffffffffu, a1, o);
        a2 += __shfl_xor_sync(0xffffffffu, a2, o);
        a3 += __shfl_xor_sync(0xffffffffu, a3, o);
    }
    if (lane == 0) {
        red[warp][0] = a0; red[warp][1] = a1;
        red[warp][2] = a2; red[warp][3] = a3;
    }
    __syncthreads();

    if (tid < SPG) {
        float s = 0.0f;
#pragma unroll
        for (int w = 0; w < NWARP; w++) s += red[w][tid];
        // ECC = 0.5 * signed h-sum + 0.5 (V - Eh - Ev + F counts = 1)
        out[img * STEPS + group * SPG + tid] = 0.5f * s + 0.5f;
    }
}

extern "C" void kernel_launch(void* const* d_in, const int* in_sizes, int n_in,
                              void* d_out, int out_size) {
    const float* x = (const float*)d_in[0];
    float* out = (float*)d_out;

    sig_cubical_ecc_kernel<<<NIMG * GROUPS, THREADS>>>(x, out);
}

// round 16
// speedup vs baseline: 1.1775x; 1.0175x over previous
#include <cuda_runtime.h>
#include <cuda_fp16.h>
#include <cstdint>

// SigCubicalEcc round 16 = round 15 body (2 independent half2 step-pair
// chains, tanh.approx.f16x2, half2 accumulate) in single-wave geometry:
// 128 thr (4 warps x 16 rows), GROUPS=8, grid=1536 <= 12 blocks/SM resident.
//
// h = tanh(100*(t_j - x)) = 2*sigma - 1 (monotone => max-decomposition holds
// with padding h = -1):  ECC_j = 0.5 * [signed h-sum over cells] + 0.5.

#define HH 64
#define WW 64
#define STEPS 32
#define GROUPS 8
#define SPG 4                   // 4 steps = 2 half2 chains
#define THREADS 128
#define NWARP 4
#define ROWS_PER_WARP 16
#define NIMG 192

__device__ __forceinline__ uint32_t h2_as_u32(__half2 v) {
    return *reinterpret_cast<uint32_t*>(&v);
}
__device__ __forceinline__ __half2 u32_as_h2(uint32_t u) {
    return *reinterpret_cast<__half2*>(&u);
}
__device__ __forceinline__ __half2 tanh2_approx(__half2 v) {
    uint32_t r, u = h2_as_u32(v);
    asm("tanh.approx.f16x2 %0, %1;" : "=r"(r) : "r"(u));
    return u32_as_h2(r);
}

struct Chain {
    __half2 sp0, sp1, mp0, mp1, acc;
};

__device__ __forceinline__ void halo_update(Chain& ch, __half2 s0, __half2 s1,
                                            __half2 sn) {
    ch.sp0 = s0; ch.sp1 = s1;
    ch.mp0 = __hmax2(s0, s1);
    ch.mp1 = __hmax2(s1, sn);
}

__device__ __forceinline__ void row_update(Chain& ch, __half2 s0, __half2 s1,
                                           __half2 sn, bool lane0) {
    __half2 m0 = __hmax2(s0, s1);
    __half2 m1 = __hmax2(s1, sn);
    __half2 eh    = __hmax2(s0, ch.sp0);
    __half2 ehsel = lane0 ? s0 : eh;             // left-boundary cancellation
    __half2 contrib =
        __hadd2(__hsub2(__hmin2(s0, s1), m1),
        __hadd2(__hsub2(__hmax2(m0, ch.mp0), ehsel),
                __hsub2(__hmax2(m1, ch.mp1), __hmax2(s1, ch.sp1))));
    ch.acc = __hadd2(ch.acc, contrib);
    ch.sp0 = s0; ch.sp1 = s1; ch.mp0 = m0; ch.mp1 = m1;
}

__global__ __launch_bounds__(THREADS, 12)
void sig_cubical_ecc_kernel(const float* __restrict__ x, float* __restrict__ out) {
    __shared__ float red[NWARP][SPG];

    const int img   = blockIdx.x >> 3;           // / GROUPS
    const int group = blockIdx.x & (GROUPS - 1);
    const int tid   = threadIdx.x;
    const int lane  = tid & 31;
    const int warp  = tid >> 5;
    const bool lane0 = (lane == 0);

    const float HL = 100.0f;                     // LAM / 2

    const int j0 = group * SPG;
    const float A0 = HL * (0.02f + (float)(j0 + 0) * (0.26f / 31.0f));
    const float A1 = HL * (0.02f + (float)(j0 + 1) * (0.26f / 31.0f));
    const float A2 = HL * (0.02f + (float)(j0 + 2) * (0.26f / 31.0f));
    const float A3 = HL * (0.02f + (float)(j0 + 3) * (0.26f / 31.0f));

    const __half2 NEG1 = __floats2half2_rn(-1.0f, -1.0f);
    const __half2 ZERO = __floats2half2_rn(0.0f, 0.0f);

    const float* xi = x + (size_t)img * (HH * WW) + 2 * lane;
    const int r0 = warp * ROWS_PER_WARP;

    Chain ca, cb;
    ca.sp0 = NEG1; ca.sp1 = NEG1; ca.mp0 = NEG1; ca.mp1 = NEG1; ca.acc = ZERO;
    cb.sp0 = NEG1; cb.sp1 = NEG1; cb.mp0 = NEG1; cb.mp1 = NEG1; cb.acc = ZERO;

    // ---- halo row r0-1 (warp 0: row -1 is padding => keep NEG1 init) ----
    if (warp > 0) {
        float2 xv = *reinterpret_cast<const float2*>(xi + (r0 - 1) * WW);
        __half2 sa0 = tanh2_approx(__floats2half2_rn(fmaf(xv.x, -HL, A0),
                                                     fmaf(xv.x, -HL, A1)));
        __half2 sa1 = tanh2_approx(__floats2half2_rn(fmaf(xv.y, -HL, A0),
                                                     fmaf(xv.y, -HL, A1)));
        __half2 sb0 = tanh2_approx(__floats2half2_rn(fmaf(xv.x, -HL, A2),
                                                     fmaf(xv.x, -HL, A3)));
        __half2 sb1 = tanh2_approx(__floats2half2_rn(fmaf(xv.y, -HL, A2),
                                                     fmaf(xv.y, -HL, A3)));
        uint32_t sna = __shfl_down_sync(0xffffffffu, h2_as_u32(sa0), 1);
        uint32_t snb = __shfl_down_sync(0xffffffffu, h2_as_u32(sb0), 1);
        halo_update(ca, sa0, sa1, (lane == 31) ? NEG1 : u32_as_h2(sna));
        halo_update(cb, sb0, sb1, (lane == 31) ? NEG1 : u32_as_h2(snb));
    }

    // ---- 16 data rows ----
#pragma unroll 4
    for (int i = 0; i < ROWS_PER_WARP; i++) {
        float2 xv = *reinterpret_cast<const float2*>(xi + (r0 + i) * WW);
        __half2 sa0 = tanh2_approx(__floats2half2_rn(fmaf(xv.x, -HL, A0),
                                                     fmaf(xv.x, -HL, A1)));
        __half2 sa1 = tanh2_approx(__floats2half2_rn(fmaf(xv.y, -HL, A0),
                                                     fmaf(xv.y, -HL, A1)));
        __half2 sb0 = tanh2_approx(__floats2half2_rn(fmaf(xv.x, -HL, A2),
                                                     fmaf(xv.x, -HL, A3)));
        __half2 sb1 = tanh2_approx(__floats2half2_rn(fmaf(xv.y, -HL, A2),
                                                     fmaf(xv.y, -HL, A3)));
        uint32_t sna = __shfl_down_sync(0xffffffffu, h2_as_u32(sa0), 1);
        uint32_t snb = __shfl_down_sync(0xffffffffu, h2_as_u32(sb0), 1);
        row_update(ca, sa0, sa1, (lane == 31) ? NEG1 : u32_as_h2(sna), lane0);
        row_update(cb, sb0, sb1, (lane == 31) ? NEG1 : u32_as_h2(snb), lane0);
    }

    // ---- bottom boundary (row below is padding) ----
    if (warp == NWARP - 1) {
        __half2 ehA = lane0 ? ZERO : ca.sp0;
        ca.acc = __hadd2(ca.acc, __hadd2(__hsub2(ca.mp0, ehA),
                                         __hsub2(ca.mp1, ca.sp1)));
        __half2 ehB = lane0 ? ZERO : cb.sp0;
        cb.acc = __hadd2(cb.acc, __hadd2(__hsub2(cb.mp0, ehB),
                                         __hsub2(cb.mp1, cb.sp1)));
    }

    // ---- convert once, warp reduce in f32, block reduce, store ----
    float2 fa = __half22float2(ca.acc);
    float2 fb = __half22float2(cb.acc);
    float a0 = fa.x, a1 = fa.y, a2 = fb.x, a3 = fb.y;
#pragma unroll
    for (int o = 16; o > 0; o >>= 1) {
        a0 += __shfl_xor_sync(0xffffffffu, a0, o);
        a1 += __shfl_xor_sync(0xffffffffu, a1, o);
        a2 += __shfl_xor_sync(0xffffffffu, a2, o);
        a3 += __shfl_xor_sync(0xffffffffu, a3, o);
    }
    if (lane == 0) {
        red[warp][0] = a0; red[warp][1] = a1;
        red[warp][2] = a2; red[warp][3] = a3;
    }
    __syncthreads();

    if (tid < SPG) {
        float s = 0.0f;
#pragma unroll
        for (int w = 0; w < NWARP; w++) s += red[w][tid];
        // ECC = 0.5 * signed h-sum + 0.5 (V - Eh - Ev + F counts = 1)
        out[img * STEPS + group * SPG + tid] = 0.5f * s + 0.5f;
    }
}

extern "C" void kernel_launch(void* const* d_in, const int* in_sizes, int n_in,
                              void* d_out, int out_size) {
    const float* x = (const float*)d_in[0];
    float* out = (float*)d_out;

    sig_cubical_ecc_kernel<<<NIMG * GROUPS, THREADS>>>(x, out);
}